// round 9
// baseline (speedup 1.0000x reference)
#include <cuda_runtime.h>
#include <cuda_fp16.h>
#include <cstdint>
#include <math.h>

#define B_ 2
#define T_ 2048
#define C_ 4096
#define H_ 32
#define D_ 128
#define M_ (B_*T_)
#define NELEM 16777216   /* 4096*4096 */

// ---------------- scratch (device globals: allocation-guard safe) -----------
__device__ __half g_xh[NELEM];               // X fp16 [M,K]
__device__ __half g_wh[4*(size_t)NELEM];     // Wq,Wk,Wv,Wo fp16, ORIGINAL [K,N] layout
__device__ __half g_qh[NELEM];               // q [b,h,t,d] fp16 (rope applied)
__device__ __half g_kh[NELEM];               // k [b,h,t,d] fp16 (rope applied)
__device__ __half g_vh[NELEM];               // v [b,h,t,d] fp16
__device__ __half g_ah[NELEM];               // attention out [b*t, h*D+d] fp16
__device__ float  g_rope[T_*64];

// ---------------- PTX helpers ------------------------------------------------
__device__ __forceinline__ uint32_t smem_u32(const void* p) {
    uint32_t a;
    asm("{ .reg .u64 t; cvta.to.shared.u64 t, %1; cvt.u32.u64 %0, t; }" : "=r"(a) : "l"(p));
    return a;
}
#define CP_ASYNC(dst, src) \
    asm volatile("cp.async.cg.shared.global [%0], [%1], 16;" :: "r"(dst), "l"(src) : "memory")
#define CP_COMMIT() asm volatile("cp.async.commit_group;" ::: "memory")
#define CP_WAIT(n)  asm volatile("cp.async.wait_group %0;" :: "n"(n) : "memory")

#define LDSM4(r0, r1, r2, r3, a) \
    asm volatile("ldmatrix.sync.aligned.m8n8.x4.shared.b16 {%0,%1,%2,%3}, [%4];" \
        : "=r"(r0), "=r"(r1), "=r"(r2), "=r"(r3) : "r"(a))
#define LDSM4T(r0, r1, r2, r3, a) \
    asm volatile("ldmatrix.sync.aligned.m8n8.x4.trans.shared.b16 {%0,%1,%2,%3}, [%4];" \
        : "=r"(r0), "=r"(r1), "=r"(r2), "=r"(r3) : "r"(a))

__device__ __forceinline__ void mma16816(float* d, const uint32_t* a, const uint32_t* b) {
    asm volatile(
        "mma.sync.aligned.m16n8k16.row.col.f32.f16.f16.f32 "
        "{%0,%1,%2,%3}, {%4,%5,%6,%7}, {%8,%9}, {%0,%1,%2,%3};\n"
        : "+f"(d[0]), "+f"(d[1]), "+f"(d[2]), "+f"(d[3])
        : "r"(a[0]), "r"(a[1]), "r"(a[2]), "r"(a[3]), "r"(b[0]), "r"(b[1]));
}

// ---------------- pre-pass kernels -------------------------------------------
__global__ void rope_kernel() {
    int i = blockIdx.x * blockDim.x + threadIdx.x;
    if (i >= T_ * 64) return;
    int t = i >> 6, j = i & 63;
    float f = 1.0f / powf(10000.0f, (float)(2 * j) * (1.0f / 128.0f));
    float m = (float)t * f;
    g_rope[i] = cosf(m) + sinf(m);
}
// one kernel converts X and all four weights: z = 0..3 -> W, z = 4 -> X
__global__ void conv_all(const float* __restrict__ X,
                         const float* __restrict__ W0, const float* __restrict__ W1,
                         const float* __restrict__ W2, const float* __restrict__ W3) {
    int z = blockIdx.y;
    const float* src = (z == 0) ? W0 : (z == 1) ? W1 : (z == 2) ? W2
                     : (z == 3) ? W3 : X;
    __half* dst = (z < 4) ? (g_wh + (size_t)z * NELEM) : g_xh;
    int i = blockIdx.x * blockDim.x + threadIdx.x;
    float4 v = *(const float4*)(src + (size_t)i * 4);
    *(__half2*)(dst + (size_t)i * 4)     = __floats2half2_rn(v.x, v.y);
    *(__half2*)(dst + (size_t)i * 4 + 2) = __floats2half2_rn(v.z, v.w);
}

// ---------------- fp16 mma GEMM (persistent CTAs) ---------------------------
// C[4096,4096] = A @ W;  A [M,K] fp16 row-major, W [K,N] fp16 row-major.
// 128x128x64 tiles, 3-stage cp.async (96KB -> 2 CTAs/SM, 16 warps/SM),
// 256 thr (8 warps 2x4, warp tile 64x32). Persistent: grid = 2*SMs, each CTA
// strides over tiles (kills ragged tail waves).
// MODE 0: A=g_xh, W=g_wh[z]; epilogue rope (z<2) + scatter fp16 q/k/v [b,h,t,d]
// MODE 1: A=g_ah, W=g_wh[3]; fp32 row-major store to Cout.
#define BM 128
#define BN 128
#define BKH 64
#define STG_A (BM*BKH*2)     /* 16384 */
#define STG   (2*STG_A)      /* 32768: A (128r x 128B) then B (64r x 256B) */
#define NT    (C_/BKH)       /* 64 */
#define GEMM_SMEM (3*STG)    /* 98304 */

template<int MODE>
__global__ void __launch_bounds__(256, 2) gemm_h(float* __restrict__ Cout, int total) {
    extern __shared__ char smc[];
    const uint32_t sb = smem_u32(smc);
    const int tid = threadIdx.x;
    const int wid = tid >> 5, lane = tid & 31;
    const int wm = (wid >> 2) * 64, wn = (wid & 3) * 32;
    const __half* A = (MODE == 0) ? g_xh : g_ah;

    for (int tile = blockIdx.x; tile < total; tile += gridDim.x) {
        const int z  = (MODE == 0) ? (tile >> 10) : 3;
        const int rr = tile & 1023;
        const int m0 = (rr & 31) * BM, n0 = (rr >> 5) * BN;
        const __half* Wm = g_wh + (size_t)z * NELEM;

        auto stage_load = [&](int kt) {
            const uint32_t sa = sb + (kt % 3) * STG;
            const int kc = kt * BKH;
            #pragma unroll
            for (int i = 0; i < 4; i++) {      // A: 128 rows x 8 chunks of 16B
                int idx = tid + i * 256;
                int r = idx >> 3, c = idx & 7;
                CP_ASYNC(sa + r * 128 + (((uint32_t)(c ^ (r & 7))) << 4),
                         A + (size_t)(m0 + r) * C_ + kc + c * 8);
            }
            #pragma unroll
            for (int i = 0; i < 4; i++) {      // B: 64 rows x 16 chunks of 16B
                int idx = tid + i * 256;
                int r = idx >> 4, c = idx & 15;
                CP_ASYNC(sa + STG_A + r * 256 + (((uint32_t)(c ^ (r & 7))) << 4),
                         Wm + (size_t)(kc + r) * C_ + n0 + c * 8);
            }
            CP_COMMIT();
        };

        float acc[4][4][4];
        #pragma unroll
        for (int i = 0; i < 4; i++)
            #pragma unroll
            for (int j = 0; j < 4; j++)
                #pragma unroll
                for (int k = 0; k < 4; k++) acc[i][j][k] = 0.f;

        __syncthreads();        // prev tile's smem reads fully done
        stage_load(0); stage_load(1);

        for (int kt = 0; kt < NT; kt++) {
            if (kt < NT - 1) { CP_WAIT(1); } else { CP_WAIT(0); }
            __syncthreads();
            if (kt + 2 < NT) stage_load(kt + 2);
            const uint32_t sa = sb + (kt % 3) * STG;
            #pragma unroll
            for (int ks = 0; ks < 4; ks++) {
                uint32_t a[4][4];
                #pragma unroll
                for (int mi = 0; mi < 4; mi++) {
                    int r = wm + mi * 16 + (lane & 15);
                    int cc = ks * 2 + (lane >> 4);
                    LDSM4(a[mi][0], a[mi][1], a[mi][2], a[mi][3],
                          sa + r * 128 + (((uint32_t)(cc ^ (r & 7))) << 4));
                }
                uint32_t b[4][2];
                #pragma unroll
                for (int np = 0; np < 2; np++) {   // trans-load from [K,N] tile
                    int r = ks * 16 + (lane & 15);
                    int c = (wn >> 3) + np * 2 + (lane >> 4);
                    uint32_t t0, t1, t2, t3;
                    LDSM4T(t0, t1, t2, t3,
                           sa + STG_A + r * 256 + (((uint32_t)(c ^ (r & 7))) << 4));
                    b[np*2][0] = t0; b[np*2][1] = t1;
                    b[np*2+1][0] = t2; b[np*2+1][1] = t3;
                }
                #pragma unroll
                for (int mi = 0; mi < 4; mi++)
                    #pragma unroll
                    for (int ni = 0; ni < 4; ni++)
                        mma16816(acc[mi][ni], a[mi], b[ni]);
            }
        }

        // epilogue (no smem use)
        #pragma unroll
        for (int mi = 0; mi < 4; mi++) {
            #pragma unroll
            for (int ni = 0; ni < 4; ni++) {
                #pragma unroll
                for (int h2 = 0; h2 < 2; h2++) {
                    int row = m0 + wm + mi * 16 + (lane >> 2) + h2 * 8;
                    int col = n0 + wn + ni * 8 + (lane & 3) * 2;
                    float v0 = acc[mi][ni][h2 * 2], v1 = acc[mi][ni][h2 * 2 + 1];
                    if (MODE == 0) {
                        int b = row >> 11, t = row & (T_ - 1);
                        int h = col >> 7,  d = col & (D_ - 1);
                        if (z < 2) {
                            v0 *= g_rope[t * 64 + (d & 63)];
                            v1 *= g_rope[t * 64 + ((d + 1) & 63)];
                        }
                        __half* dst = (z == 0) ? g_qh : (z == 1) ? g_kh : g_vh;
                        *(__half2*)(dst + (size_t)((b * H_ + h) * T_ + t) * D_ + d) =
                            __floats2half2_rn(v0, v1);
                    } else {
                        *(float2*)(Cout + (size_t)row * C_ + col) = make_float2(v0, v1);
                    }
                }
            }
        }
    }
}

// ---------------- fp16 mma flash attention (heavy-first, double-buffered) ---
// CTA: 128 thr (4 warps), q tile 64 rows, kv tiles 64 keys, double-buffered
// K/V slots. grid (T/64, B*H); blocks with the longest causal span run first.
// Output fp16 -> g_ah [b*t, h*D+d].
#define ROWB 272     /* 136 halves per Q/K/V smem row (16B skew) */
#define PROWB 144    /* 72 halves per P smem row */
#define QSZ (64*ROWB)          /* 17408 */
#define ATT_SMEM (5*QSZ)       /* Q + 2K + 2V = 87040 */

__global__ void __launch_bounds__(128, 2) attn_h() {
    extern __shared__ char smc[];
    const uint32_t sb = smem_u32(smc);
    const uint32_t sQ = sb;
    const int tid = threadIdx.x, w = tid >> 5, lane = tid & 31;
    const int bh = blockIdx.y;
    const int q0 = ((int)gridDim.x - 1 - (int)blockIdx.x) * 64;  // heavy first
    const __half* Qg = g_qh + (size_t)bh * T_ * D_;
    const __half* Kg = g_kh + (size_t)bh * T_ * D_;
    const __half* Vg = g_vh + (size_t)bh * T_ * D_;

    auto loadKV = [&](int tile, int slot) {
        const uint32_t sK = sb + QSZ + slot * QSZ;
        const uint32_t sV = sb + 3 * QSZ + slot * QSZ;
        const int t0 = tile * 64;
        #pragma unroll
        for (int i = 0; i < 8; i++) {
            int idx = tid + i * 128;
            int r = idx >> 4, c = idx & 15;
            CP_ASYNC(sK + r * ROWB + c * 16, Kg + (size_t)(t0 + r) * D_ + c * 8);
        }
        #pragma unroll
        for (int i = 0; i < 8; i++) {
            int idx = tid + i * 128;
            int r = idx >> 4, c = idx & 15;
            CP_ASYNC(sV + r * ROWB + c * 16, Vg + (size_t)(t0 + r) * D_ + c * 8);
        }
        CP_COMMIT();
    };

    // stage Q (group 0), then KV tile 0 (group 1)
    #pragma unroll
    for (int i = 0; i < 8; i++) {
        int idx = tid + i * 128;
        int r = idx >> 4, c = idx & 15;
        CP_ASYNC(sQ + r * ROWB + c * 16, Qg + (size_t)(q0 + r) * D_ + c * 8);
    }
    CP_COMMIT();
    loadKV(0, 0);
    CP_WAIT(1);                 // Q resident
    __syncthreads();

    uint32_t qf[8][4];
    #pragma unroll
    for (int ks = 0; ks < 8; ks++) {
        int r = w * 16 + (lane & 15), cc = ks * 2 + (lane >> 4);
        LDSM4(qf[ks][0], qf[ks][1], qf[ks][2], qf[ks][3], sQ + r * ROWB + cc * 16);
    }

    float oacc[16][4];
    #pragma unroll
    for (int i = 0; i < 16; i++)
        #pragma unroll
        for (int j = 0; j < 4; j++) oacc[i][j] = 0.f;
    float mrow[2] = {-INFINITY, -INFINITY}, lrow[2] = {0.f, 0.f};
    const float scale = 0.08838834764831845f;
    const int r0 = lane >> 2, c0 = (lane & 3) * 2;
    const int ntiles = q0 / 64 + 1;

    for (int it = 0; it < ntiles; it++) {
        __syncthreads();        // prev compute done (slot (it+1)&1 free; Q frags read)
        if (it + 1 < ntiles) { loadKV(it + 1, (it + 1) & 1); CP_WAIT(1); }
        else                 { CP_WAIT(0); }
        __syncthreads();        // tile it resident for all threads

        const uint32_t sK = sb + QSZ + (it & 1) * QSZ;
        const uint32_t sV = sb + 3 * QSZ + (it & 1) * QSZ;

        // S = Q K^T  (16x64 per warp)
        float sacc[8][4];
        #pragma unroll
        for (int f = 0; f < 8; f++)
            #pragma unroll
            for (int j = 0; j < 4; j++) sacc[f][j] = 0.f;
        #pragma unroll
        for (int ks = 0; ks < 8; ks++) {
            uint32_t b[8][2];
            #pragma unroll
            for (int np = 0; np < 4; np++) {
                int r = np * 16 + (lane & 15), cc = ks * 2 + (lane >> 4);
                uint32_t t0_, t1_, t2_, t3_;
                LDSM4(t0_, t1_, t2_, t3_, sK + r * ROWB + cc * 16);
                b[np*2][0] = t0_; b[np*2+1][0] = t1_;
                b[np*2][1] = t2_; b[np*2+1][1] = t3_;
            }
            #pragma unroll
            for (int f = 0; f < 8; f++) mma16816(sacc[f], qf[ks], b[f]);
        }

        // online softmax
        const bool diag = (it == ntiles - 1);
        float mt[2] = {-INFINITY, -INFINITY};
        #pragma unroll
        for (int f = 0; f < 8; f++) {
            #pragma unroll
            for (int j = 0; j < 4; j++) {
                float v = sacc[f][j] * scale;
                if (diag) {
                    int col = f * 8 + c0 + (j & 1);
                    int rr  = w * 16 + r0 + (j >> 1) * 8;
                    if (col > rr) v = -1e30f;
                }
                sacc[f][j] = v;
                mt[j >> 1] = fmaxf(mt[j >> 1], v);
            }
        }
        float corr[2], rs[2] = {0.f, 0.f};
        #pragma unroll
        for (int h2 = 0; h2 < 2; h2++) {
            mt[h2] = fmaxf(mt[h2], __shfl_xor_sync(0xffffffffu, mt[h2], 1));
            mt[h2] = fmaxf(mt[h2], __shfl_xor_sync(0xffffffffu, mt[h2], 2));
            float mn = fmaxf(mrow[h2], mt[h2]);
            corr[h2] = __expf(mrow[h2] - mn);
            mrow[h2] = mn;
        }
        #pragma unroll
        for (int f = 0; f < 8; f++) {
            #pragma unroll
            for (int j = 0; j < 4; j++) {
                float p = __expf(sacc[f][j] - mrow[j >> 1]);
                sacc[f][j] = p;
                rs[j >> 1] += p;
            }
        }
        #pragma unroll
        for (int h2 = 0; h2 < 2; h2++) {
            rs[h2] += __shfl_xor_sync(0xffffffffu, rs[h2], 1);
            rs[h2] += __shfl_xor_sync(0xffffffffu, rs[h2], 2);
            lrow[h2] = lrow[h2] * corr[h2] + rs[h2];
        }
        #pragma unroll
        for (int f = 0; f < 16; f++)
            #pragma unroll
            for (int j = 0; j < 4; j++) oacc[f][j] *= corr[j >> 1];

        // P -> smem fp16 (per-warp private rows overlaying Q)
        __syncwarp();
        #pragma unroll
        for (int f = 0; f < 8; f++) {
            #pragma unroll
            for (int h2 = 0; h2 < 2; h2++) {
                uint32_t off = (uint32_t)((w * 16 + r0 + h2 * 8) * PROWB + (f * 8 + c0) * 2);
                *(__half2*)(smc + off) = __floats2half2_rn(sacc[f][h2*2], sacc[f][h2*2+1]);
            }
        }
        __syncwarp();

        // O += P V
        #pragma unroll
        for (int ks = 0; ks < 4; ks++) {
            uint32_t a[4];
            {
                int r = w * 16 + (lane & 15), cc = ks * 2 + (lane >> 4);
                LDSM4(a[0], a[1], a[2], a[3], sQ + (uint32_t)(r * PROWB + cc * 16));
            }
            #pragma unroll
            for (int dp = 0; dp < 8; dp++) {
                int vr = ks * 16 + (lane & 15), vc = dp * 2 + (lane >> 4);
                uint32_t t0_, t1_, t2_, t3_;
                LDSM4T(t0_, t1_, t2_, t3_, sV + vr * ROWB + vc * 16);
                uint32_t b0[2] = {t0_, t1_}, b1[2] = {t2_, t3_};
                mma16816(oacc[dp*2],   a, b0);
                mma16816(oacc[dp*2+1], a, b1);
            }
        }
    }

    // epilogue
    float inv[2] = {1.f / lrow[0], 1.f / lrow[1]};
    const int bq = bh >> 5, hh = bh & 31;
    #pragma unroll
    for (int dp = 0; dp < 16; dp++) {
        #pragma unroll
        for (int h2 = 0; h2 < 2; h2++) {
            int row = q0 + w * 16 + r0 + h2 * 8;
            int col = hh * D_ + dp * 8 + c0;
            *(__half2*)(g_ah + (size_t)(bq * T_ + row) * C_ + col) =
                __floats2half2_rn(oacc[dp][h2*2] * inv[h2], oacc[dp][h2*2+1] * inv[h2]);
        }
    }
}

// ---------------- launch -----------------------------------------------------
extern "C" void kernel_launch(void* const* d_in, const int* in_sizes, int n_in,
                              void* d_out, int out_size) {
    const float* X  = (const float*)d_in[0];
    const float* Wq = (const float*)d_in[1];
    const float* Wk = (const float*)d_in[2];
    const float* Wv = (const float*)d_in[3];
    const float* Wo = (const float*)d_in[4];
    float* out = (float*)d_out;

    int nsm = 148;
    cudaDeviceGetAttribute(&nsm, cudaDevAttrMultiProcessorCount, 0);
    const int pgrid = nsm * 2;   // 2 CTAs/SM resident

    cudaFuncSetAttribute(gemm_h<0>, cudaFuncAttributeMaxDynamicSharedMemorySize, GEMM_SMEM);
    cudaFuncSetAttribute(gemm_h<1>, cudaFuncAttributeMaxDynamicSharedMemorySize, GEMM_SMEM);
    cudaFuncSetAttribute(attn_h,    cudaFuncAttributeMaxDynamicSharedMemorySize, ATT_SMEM);

    rope_kernel<<<(T_ * 64 + 255) / 256, 256>>>();
    conv_all<<<dim3(NELEM / 1024, 5), 256>>>(X, Wq, Wk, Wv, Wo);

    gemm_h<0><<<pgrid, 256, GEMM_SMEM>>>(nullptr, 3072);
    attn_h<<<dim3(T_ / 64, B_ * H_), 128, ATT_SMEM>>>();
    gemm_h<1><<<pgrid, 256, GEMM_SMEM>>>(out, 1024);
}

// round 10
// speedup vs baseline: 1.0534x; 1.0534x over previous
#include <cuda_runtime.h>
#include <cuda_fp16.h>
#include <cstdint>
#include <math.h>

#define B_ 2
#define T_ 2048
#define C_ 4096
#define H_ 32
#define D_ 128
#define M_ (B_*T_)
#define NELEM 16777216   /* 4096*4096 */

// ---------------- scratch (device globals: allocation-guard safe) -----------
__device__ __half g_xh[NELEM];               // X fp16 [M,K]
__device__ __half g_wh[4*(size_t)NELEM];     // Wq,Wk,Wv,Wo fp16, ORIGINAL [K,N] layout
__device__ __half g_qh[NELEM];               // q [b,h,t,d] fp16 (rope applied)
__device__ __half g_kh[NELEM];               // k [b,h,t,d] fp16 (rope applied)
__device__ __half g_vh[NELEM];               // v [b,h,t,d] fp16
__device__ __half g_ah[NELEM];               // attention out [b*t, h*D+d] fp16
__device__ float  g_rope[T_*64];

// ---------------- PTX helpers ------------------------------------------------
__device__ __forceinline__ uint32_t smem_u32(const void* p) {
    uint32_t a;
    asm("{ .reg .u64 t; cvta.to.shared.u64 t, %1; cvt.u32.u64 %0, t; }" : "=r"(a) : "l"(p));
    return a;
}
#define CP_ASYNC(dst, src) \
    asm volatile("cp.async.cg.shared.global [%0], [%1], 16;" :: "r"(dst), "l"(src) : "memory")
#define CP_COMMIT() asm volatile("cp.async.commit_group;" ::: "memory")
#define CP_WAIT(n)  asm volatile("cp.async.wait_group %0;" :: "n"(n) : "memory")

#define LDSM4(r0, r1, r2, r3, a) \
    asm volatile("ldmatrix.sync.aligned.m8n8.x4.shared.b16 {%0,%1,%2,%3}, [%4];" \
        : "=r"(r0), "=r"(r1), "=r"(r2), "=r"(r3) : "r"(a))
#define LDSM4T(r0, r1, r2, r3, a) \
    asm volatile("ldmatrix.sync.aligned.m8n8.x4.trans.shared.b16 {%0,%1,%2,%3}, [%4];" \
        : "=r"(r0), "=r"(r1), "=r"(r2), "=r"(r3) : "r"(a))

__device__ __forceinline__ void mma16816(float* d, const uint32_t* a, const uint32_t* b) {
    asm volatile(
        "mma.sync.aligned.m16n8k16.row.col.f32.f16.f16.f32 "
        "{%0,%1,%2,%3}, {%4,%5,%6,%7}, {%8,%9}, {%0,%1,%2,%3};\n"
        : "+f"(d[0]), "+f"(d[1]), "+f"(d[2]), "+f"(d[3])
        : "r"(a[0]), "r"(a[1]), "r"(a[2]), "r"(a[3]), "r"(b[0]), "r"(b[1]));
}
__device__ __forceinline__ uint32_t h2b(__half2 h) {
    uint32_t u; asm("mov.b32 %0, %1;" : "=r"(u) : "r"(*(uint32_t*)&h)); return u;
}

// ---------------- pre-pass kernels -------------------------------------------
__global__ void rope_kernel() {
    int i = blockIdx.x * blockDim.x + threadIdx.x;
    if (i >= T_ * 64) return;
    int t = i >> 6, j = i & 63;
    float f = 1.0f / powf(10000.0f, (float)(2 * j) * (1.0f / 128.0f));
    float m = (float)t * f;
    g_rope[i] = cosf(m) + sinf(m);
}
// one kernel converts X and all four weights: z = 0..3 -> W, z = 4 -> X
__global__ void conv_all(const float* __restrict__ X,
                         const float* __restrict__ W0, const float* __restrict__ W1,
                         const float* __restrict__ W2, const float* __restrict__ W3) {
    int z = blockIdx.y;
    const float* src = (z == 0) ? W0 : (z == 1) ? W1 : (z == 2) ? W2
                     : (z == 3) ? W3 : X;
    __half* dst = (z < 4) ? (g_wh + (size_t)z * NELEM) : g_xh;
    int i = blockIdx.x * blockDim.x + threadIdx.x;
    float4 v = *(const float4*)(src + (size_t)i * 4);
    *(__half2*)(dst + (size_t)i * 4)     = __floats2half2_rn(v.x, v.y);
    *(__half2*)(dst + (size_t)i * 4 + 2) = __floats2half2_rn(v.z, v.w);
}

// ---------------- fp16 mma GEMM (R7-proven config: grid launch) -------------
// C[4096,4096] = A @ W;  A [M,K] fp16 row-major, W [K,N] fp16 row-major.
// 128x128x64 tiles, 3-stage cp.async (96KB -> 2 CTAs/SM, 16 warps/SM).
// 256 thr (8 warps 2x4, warp tile 64x32). A frags via ldmatrix, B frags via
// ldmatrix.trans on [K,N] tiles.
// MODE 0: A=g_xh, W=g_wh[z]; epilogue rope (z<2) + scatter fp16 q/k/v [b,h,t,d]
// MODE 1: A=g_ah, W=g_wh[3]; fp32 row-major store to Cout.
#define BM 128
#define BN 128
#define BKH 64
#define STG_A (BM*BKH*2)     /* 16384 */
#define STG   (2*STG_A)      /* 32768: A (128r x 128B) then B (64r x 256B) */
#define NT    (C_/BKH)       /* 64 */
#define GEMM_SMEM (3*STG)    /* 98304 */

template<int MODE>
__global__ void __launch_bounds__(256, 2) gemm_h(float* __restrict__ Cout) {
    extern __shared__ char smc[];
    const uint32_t sb = smem_u32(smc);
    const int tid = threadIdx.x;
    const int m0 = blockIdx.x * BM, n0 = blockIdx.y * BN;
    const int z = (MODE == 0) ? blockIdx.z : 3;
    const __half* A  = (MODE == 0) ? g_xh : g_ah;
    const __half* Wm = g_wh + (size_t)z * NELEM;

    auto stage_load = [&](int kt) {
        const uint32_t sa = sb + (kt % 3) * STG;
        const int kc = kt * BKH;
        #pragma unroll
        for (int i = 0; i < 4; i++) {          // A: 128 rows x 8 chunks of 16B
            int idx = tid + i * 256;
            int r = idx >> 3, c = idx & 7;
            CP_ASYNC(sa + r * 128 + (((uint32_t)(c ^ (r & 7))) << 4),
                     A + (size_t)(m0 + r) * C_ + kc + c * 8);
        }
        #pragma unroll
        for (int i = 0; i < 4; i++) {          // B: 64 rows x 16 chunks of 16B
            int idx = tid + i * 256;
            int r = idx >> 4, c = idx & 15;
            CP_ASYNC(sa + STG_A + r * 256 + (((uint32_t)(c ^ (r & 7))) << 4),
                     Wm + (size_t)(kc + r) * C_ + n0 + c * 8);
        }
        CP_COMMIT();
    };

    const int wid = tid >> 5, lane = tid & 31;
    const int wm = (wid >> 2) * 64, wn = (wid & 3) * 32;

    float acc[4][4][4];
    #pragma unroll
    for (int i = 0; i < 4; i++)
        #pragma unroll
        for (int j = 0; j < 4; j++)
            #pragma unroll
            for (int k = 0; k < 4; k++) acc[i][j][k] = 0.f;

    stage_load(0); stage_load(1);

    for (int kt = 0; kt < NT; kt++) {
        if (kt < NT - 1) { CP_WAIT(1); } else { CP_WAIT(0); }
        __syncthreads();
        if (kt + 2 < NT) stage_load(kt + 2);
        const uint32_t sa = sb + (kt % 3) * STG;
        #pragma unroll
        for (int ks = 0; ks < 4; ks++) {
            uint32_t a[4][4];
            #pragma unroll
            for (int mi = 0; mi < 4; mi++) {
                int r = wm + mi * 16 + (lane & 15);
                int cc = ks * 2 + (lane >> 4);
                LDSM4(a[mi][0], a[mi][1], a[mi][2], a[mi][3],
                      sa + r * 128 + (((uint32_t)(cc ^ (r & 7))) << 4));
            }
            uint32_t b[4][2];
            #pragma unroll
            for (int np = 0; np < 2; np++) {   // trans-load from [K,N] tile
                int r = ks * 16 + (lane & 15);
                int c = (wn >> 3) + np * 2 + (lane >> 4);
                uint32_t t0, t1, t2, t3;
                LDSM4T(t0, t1, t2, t3,
                       sa + STG_A + r * 256 + (((uint32_t)(c ^ (r & 7))) << 4));
                b[np*2][0] = t0; b[np*2][1] = t1;
                b[np*2+1][0] = t2; b[np*2+1][1] = t3;
            }
            #pragma unroll
            for (int mi = 0; mi < 4; mi++)
                #pragma unroll
                for (int ni = 0; ni < 4; ni++)
                    mma16816(acc[mi][ni], a[mi], b[ni]);
        }
    }

    // epilogue
    #pragma unroll
    for (int mi = 0; mi < 4; mi++) {
        #pragma unroll
        for (int ni = 0; ni < 4; ni++) {
            #pragma unroll
            for (int h2 = 0; h2 < 2; h2++) {
                int row = m0 + wm + mi * 16 + (lane >> 2) + h2 * 8;
                int col = n0 + wn + ni * 8 + (lane & 3) * 2;
                float v0 = acc[mi][ni][h2 * 2], v1 = acc[mi][ni][h2 * 2 + 1];
                if (MODE == 0) {
                    int b = row >> 11, t = row & (T_ - 1);
                    int h = col >> 7,  d = col & (D_ - 1);
                    if (z < 2) {
                        v0 *= g_rope[t * 64 + (d & 63)];
                        v1 *= g_rope[t * 64 + ((d + 1) & 63)];
                    }
                    __half* dst = (z == 0) ? g_qh : (z == 1) ? g_kh : g_vh;
                    *(__half2*)(dst + (size_t)((b * H_ + h) * T_ + t) * D_ + d) =
                        __floats2half2_rn(v0, v1);
                } else {
                    *(float2*)(Cout + (size_t)row * C_ + col) = make_float2(v0, v1);
                }
            }
        }
    }
}

// ---------------- fp16 mma flash attention (register-resident P) ------------
// CTA: 128 thr (4 warps), q tile 64 rows, kv tiles 64 keys, double-buffered
// K/V slots, heavy blocks first. The P = softmax(S) matrix is converted from
// the S accumulator fragments DIRECTLY into A-fragments of the P·V mma
// (C-layout of m16n8k16 == A-layout) — no smem round-trip.
// Output fp16 -> g_ah [b*t, h*D+d].
#define ROWB 272     /* 136 halves per Q/K/V smem row (16B skew) */
#define QSZ (64*ROWB)          /* 17408 */
#define ATT_SMEM (5*QSZ)       /* Q + 2K + 2V = 87040 */

__global__ void __launch_bounds__(128, 2) attn_h() {
    extern __shared__ char smc[];
    const uint32_t sb = smem_u32(smc);
    const uint32_t sQ = sb;
    const int tid = threadIdx.x, w = tid >> 5, lane = tid & 31;
    const int bh = blockIdx.y;
    const int q0 = ((int)gridDim.x - 1 - (int)blockIdx.x) * 64;  // heavy first
    const __half* Qg = g_qh + (size_t)bh * T_ * D_;
    const __half* Kg = g_kh + (size_t)bh * T_ * D_;
    const __half* Vg = g_vh + (size_t)bh * T_ * D_;

    auto loadKV = [&](int tile, int slot) {
        const uint32_t sK = sb + QSZ + slot * QSZ;
        const uint32_t sV = sb + 3 * QSZ + slot * QSZ;
        const int t0 = tile * 64;
        #pragma unroll
        for (int i = 0; i < 8; i++) {
            int idx = tid + i * 128;
            int r = idx >> 4, c = idx & 15;
            CP_ASYNC(sK + r * ROWB + c * 16, Kg + (size_t)(t0 + r) * D_ + c * 8);
        }
        #pragma unroll
        for (int i = 0; i < 8; i++) {
            int idx = tid + i * 128;
            int r = idx >> 4, c = idx & 15;
            CP_ASYNC(sV + r * ROWB + c * 16, Vg + (size_t)(t0 + r) * D_ + c * 8);
        }
        CP_COMMIT();
    };

    // stage Q (group 0), then KV tile 0 (group 1)
    #pragma unroll
    for (int i = 0; i < 8; i++) {
        int idx = tid + i * 128;
        int r = idx >> 4, c = idx & 15;
        CP_ASYNC(sQ + r * ROWB + c * 16, Qg + (size_t)(q0 + r) * D_ + c * 8);
    }
    CP_COMMIT();
    loadKV(0, 0);
    CP_WAIT(1);                 // Q resident
    __syncthreads();

    uint32_t qf[8][4];
    #pragma unroll
    for (int ks = 0; ks < 8; ks++) {
        int r = w * 16 + (lane & 15), cc = ks * 2 + (lane >> 4);
        LDSM4(qf[ks][0], qf[ks][1], qf[ks][2], qf[ks][3], sQ + r * ROWB + cc * 16);
    }

    float oacc[16][4];
    #pragma unroll
    for (int i = 0; i < 16; i++)
        #pragma unroll
        for (int j = 0; j < 4; j++) oacc[i][j] = 0.f;
    float mrow[2] = {-INFINITY, -INFINITY}, lrow[2] = {0.f, 0.f};
    const float scale = 0.08838834764831845f;
    const int r0 = lane >> 2, c0 = (lane & 3) * 2;
    const int ntiles = q0 / 64 + 1;

    for (int it = 0; it < ntiles; it++) {
        __syncthreads();        // prev compute done (slot (it+1)&1 free)
        if (it + 1 < ntiles) { loadKV(it + 1, (it + 1) & 1); CP_WAIT(1); }
        else                 { CP_WAIT(0); }
        __syncthreads();        // tile it resident for all threads

        const uint32_t sK = sb + QSZ + (it & 1) * QSZ;
        const uint32_t sV = sb + 3 * QSZ + (it & 1) * QSZ;

        // S = Q K^T  (16x64 per warp)
        float sacc[8][4];
        #pragma unroll
        for (int f = 0; f < 8; f++)
            #pragma unroll
            for (int j = 0; j < 4; j++) sacc[f][j] = 0.f;
        #pragma unroll
        for (int ks = 0; ks < 8; ks++) {
            uint32_t b[8][2];
            #pragma unroll
            for (int np = 0; np < 4; np++) {
                int r = np * 16 + (lane & 15), cc = ks * 2 + (lane >> 4);
                uint32_t t0_, t1_, t2_, t3_;
                LDSM4(t0_, t1_, t2_, t3_, sK + r * ROWB + cc * 16);
                b[np*2][0] = t0_; b[np*2+1][0] = t1_;
                b[np*2][1] = t2_; b[np*2+1][1] = t3_;
            }
            #pragma unroll
            for (int f = 0; f < 8; f++) mma16816(sacc[f], qf[ks], b[f]);
        }

        // online softmax
        const bool diag = (it == ntiles - 1);
        float mt[2] = {-INFINITY, -INFINITY};
        #pragma unroll
        for (int f = 0; f < 8; f++) {
            #pragma unroll
            for (int j = 0; j < 4; j++) {
                float v = sacc[f][j] * scale;
                if (diag) {
                    int col = f * 8 + c0 + (j & 1);
                    int rr  = w * 16 + r0 + (j >> 1) * 8;
                    if (col > rr) v = -1e30f;
                }
                sacc[f][j] = v;
                mt[j >> 1] = fmaxf(mt[j >> 1], v);
            }
        }
        float corr[2], rs[2] = {0.f, 0.f};
        #pragma unroll
        for (int h2 = 0; h2 < 2; h2++) {
            mt[h2] = fmaxf(mt[h2], __shfl_xor_sync(0xffffffffu, mt[h2], 1));
            mt[h2] = fmaxf(mt[h2], __shfl_xor_sync(0xffffffffu, mt[h2], 2));
            float mn = fmaxf(mrow[h2], mt[h2]);
            corr[h2] = __expf(mrow[h2] - mn);
            mrow[h2] = mn;
        }
        #pragma unroll
        for (int f = 0; f < 8; f++) {
            #pragma unroll
            for (int j = 0; j < 4; j++) {
                float p = __expf(sacc[f][j] - mrow[j >> 1]);
                sacc[f][j] = p;
                rs[j >> 1] += p;
            }
        }
        #pragma unroll
        for (int h2 = 0; h2 < 2; h2++) {
            rs[h2] += __shfl_xor_sync(0xffffffffu, rs[h2], 1);
            rs[h2] += __shfl_xor_sync(0xffffffffu, rs[h2], 2);
            lrow[h2] = lrow[h2] * corr[h2] + rs[h2];
        }
        #pragma unroll
        for (int f = 0; f < 16; f++)
            #pragma unroll
            for (int j = 0; j < 4; j++) oacc[f][j] *= corr[j >> 1];

        // O += P V  — P converted in-register: C-frag layout == A-frag layout
        #pragma unroll
        for (int ks = 0; ks < 4; ks++) {
            uint32_t a[4];
            a[0] = h2b(__floats2half2_rn(sacc[2*ks][0],   sacc[2*ks][1]));
            a[1] = h2b(__floats2half2_rn(sacc[2*ks][2],   sacc[2*ks][3]));
            a[2] = h2b(__floats2half2_rn(sacc[2*ks+1][0], sacc[2*ks+1][1]));
            a[3] = h2b(__floats2half2_rn(sacc[2*ks+1][2], sacc[2*ks+1][3]));
            #pragma unroll
            for (int dp = 0; dp < 8; dp++) {
                int vr = ks * 16 + (lane & 15), vc = dp * 2 + (lane >> 4);
                uint32_t t0_, t1_, t2_, t3_;
                LDSM4T(t0_, t1_, t2_, t3_, sV + vr * ROWB + vc * 16);
                uint32_t b0[2] = {t0_, t1_}, b1[2] = {t2_, t3_};
                mma16816(oacc[dp*2],   a, b0);
                mma16816(oacc[dp*2+1], a, b1);
            }
        }
    }

    // epilogue
    float inv[2] = {1.f / lrow[0], 1.f / lrow[1]};
    const int bq = bh >> 5, hh = bh & 31;
    #pragma unroll
    for (int dp = 0; dp < 16; dp++) {
        #pragma unroll
        for (int h2 = 0; h2 < 2; h2++) {
            int row = q0 + w * 16 + r0 + h2 * 8;
            int col = hh * D_ + dp * 8 + c0;
            *(__half2*)(g_ah + (size_t)(bq * T_ + row) * C_ + col) =
                __floats2half2_rn(oacc[dp][h2*2] * inv[h2], oacc[dp][h2*2+1] * inv[h2]);
        }
    }
}

// ---------------- launch -----------------------------------------------------
extern "C" void kernel_launch(void* const* d_in, const int* in_sizes, int n_in,
                              void* d_out, int out_size) {
    const float* X  = (const float*)d_in[0];
    const float* Wq = (const float*)d_in[1];
    const float* Wk = (const float*)d_in[2];
    const float* Wv = (const float*)d_in[3];
    const float* Wo = (const float*)d_in[4];
    float* out = (float*)d_out;

    cudaFuncSetAttribute(gemm_h<0>, cudaFuncAttributeMaxDynamicSharedMemorySize, GEMM_SMEM);
    cudaFuncSetAttribute(gemm_h<1>, cudaFuncAttributeMaxDynamicSharedMemorySize, GEMM_SMEM);
    cudaFuncSetAttribute(attn_h,    cudaFuncAttributeMaxDynamicSharedMemorySize, ATT_SMEM);

    rope_kernel<<<(T_ * 64 + 255) / 256, 256>>>();
    conv_all<<<dim3(NELEM / 1024, 5), 256>>>(X, Wq, Wk, Wv, Wo);

    gemm_h<0><<<dim3(M_ / BM, C_ / BN, 3), 256, GEMM_SMEM>>>(nullptr);
    attn_h<<<dim3(T_ / 64, B_ * H_), 128, ATT_SMEM>>>();
    gemm_h<1><<<dim3(M_ / BM, C_ / BN, 1), 256, GEMM_SMEM>>>(out);
}